// round 1
// baseline (speedup 1.0000x reference)
#include <cuda_runtime.h>

#define H 4096
#define E 8
#define H4 (H / 4)          // 1024 float4 per row
#define TPB 256

__device__ int g_idx;

// Kernel 1: router logits + argmax -> g_idx. One block, 8 warps (one per expert).
__global__ void router_argmax_kernel(const float* __restrict__ x,
                                     const float* __restrict__ router_w,
                                     const float* __restrict__ router_b) {
    int wid = threadIdx.x >> 5;
    int lane = threadIdx.x & 31;

    const float4* x4 = (const float4*)x;
    const float4* w4 = (const float4*)(router_w + (size_t)wid * H);

    float s = 0.f;
    #pragma unroll 4
    for (int i = lane; i < H4; i += 32) {
        float4 a = x4[i];
        float4 b = w4[i];
        s += a.x * b.x + a.y * b.y + a.z * b.z + a.w * b.w;
    }
    #pragma unroll
    for (int o = 16; o > 0; o >>= 1) s += __shfl_xor_sync(0xFFFFFFFFu, s, o);

    __shared__ float logits[E];
    if (lane == 0) logits[wid] = s + router_b[wid];
    __syncthreads();

    if (threadIdx.x == 0) {
        int best = 0;
        float bv = logits[0];
        #pragma unroll
        for (int e = 1; e < E; e++) {
            if (logits[e] > bv) { bv = logits[e]; best = e; }  // strict > == first-max (jnp.argmax)
        }
        g_idx = best;
    }
}

// Kernel 2: one block per output row. Dot x against expert_w[idx][row,:] and
// gate_w[row,:] (each 16 KB, coalesced float4), then fused epilogue.
__global__ void __launch_bounds__(TPB) gate_mix_kernel(
    const float* __restrict__ x,
    const float* __restrict__ expert_w,
    const float* __restrict__ expert_b,
    const float* __restrict__ gate_w,
    const float* __restrict__ gate_b,
    float* __restrict__ out) {

    const int row = blockIdx.x;
    const int idx = g_idx;

    __shared__ float4 xs[H4];   // 16 KB: x cached in smem
    const float4* x4 = (const float4*)x;
    for (int i = threadIdx.x; i < H4; i += TPB) xs[i] = x4[i];
    __syncthreads();

    const float4* e4 = (const float4*)(expert_w + ((size_t)idx * H + row) * H);
    const float4* g4 = (const float4*)(gate_w + (size_t)row * H);

    float se = 0.f, sg = 0.f;
    #pragma unroll 4
    for (int i = threadIdx.x; i < H4; i += TPB) {
        float4 a = xs[i];
        float4 e = e4[i];
        float4 g = g4[i];
        se += a.x * e.x + a.y * e.y + a.z * e.z + a.w * e.w;
        sg += a.x * g.x + a.y * g.y + a.z * g.z + a.w * g.w;
    }

    #pragma unroll
    for (int o = 16; o > 0; o >>= 1) {
        se += __shfl_xor_sync(0xFFFFFFFFu, se, o);
        sg += __shfl_xor_sync(0xFFFFFFFFu, sg, o);
    }

    __shared__ float re[TPB / 32], rg[TPB / 32];
    int wid = threadIdx.x >> 5;
    int lane = threadIdx.x & 31;
    if (lane == 0) { re[wid] = se; rg[wid] = sg; }
    __syncthreads();

    if (threadIdx.x == 0) {
        float SE = 0.f, SG = 0.f;
        #pragma unroll
        for (int w = 0; w < TPB / 32; w++) { SE += re[w]; SG += rg[w]; }
        float mix = tanhf(SE + expert_b[(size_t)idx * H + row]);
        float z = SG + gate_b[row];
        float g = 1.f / (1.f + expf(-z));
        float xv = x[row];
        out[row] = g * mix + (1.f - g) * xv;
    }
}

extern "C" void kernel_launch(void* const* d_in, const int* in_sizes, int n_in,
                              void* d_out, int out_size) {
    const float* x        = (const float*)d_in[0];  // [1, H]
    const float* expert_w = (const float*)d_in[1];  // [E, H, H]
    const float* expert_b = (const float*)d_in[2];  // [E, H]
    const float* router_w = (const float*)d_in[3];  // [E, H]
    const float* router_b = (const float*)d_in[4];  // [E]
    const float* gate_w   = (const float*)d_in[5];  // [H, H]
    const float* gate_b   = (const float*)d_in[6];  // [H]
    float* out = (float*)d_out;                     // [1, H]

    router_argmax_kernel<<<1, 256>>>(x, router_w, router_b);
    gate_mix_kernel<<<H, TPB>>>(x, expert_w, expert_b, gate_w, gate_b, out);
}

// round 2
// speedup vs baseline: 1.2712x; 1.2712x over previous
#include <cuda_runtime.h>

#define H 4096
#define E 8
#define H4 (H / 4)          // 1024 float4 per row
#define TPB 256
#define ITERS (H4 / TPB)    // 4

__device__ int g_idx;

// Kernel 1: router logits + argmax -> g_idx.
// 1024 threads: 4 warps per expert (split-K), smem reduce, argmax by thread 0.
__global__ void __launch_bounds__(1024) router_argmax_kernel(
        const float* __restrict__ x,
        const float* __restrict__ router_w,
        const float* __restrict__ router_b) {
    const int wid  = threadIdx.x >> 5;   // 0..31
    const int lane = threadIdx.x & 31;
    const int expert  = wid >> 2;        // 0..7
    const int quarter = wid & 3;         // 0..3

    const float4* x4 = (const float4*)x;
    const float4* w4 = (const float4*)(router_w + (size_t)expert * H);

    float s = 0.f;
    // strided split-K: lane + 32*quarter, stride 128 -> 8 iterations
    #pragma unroll
    for (int i = lane + 32 * quarter; i < H4; i += 128) {
        float4 a = x4[i];
        float4 b = w4[i];
        s += a.x * b.x + a.y * b.y + a.z * b.z + a.w * b.w;
    }
    #pragma unroll
    for (int o = 16; o > 0; o >>= 1) s += __shfl_xor_sync(0xFFFFFFFFu, s, o);

    __shared__ float part[32];
    if (lane == 0) part[wid] = s;
    __syncthreads();

    if (threadIdx.x == 0) {
        int best = 0;
        float bv = -1e30f;
        #pragma unroll
        for (int e = 0; e < E; e++) {
            float v = part[4*e] + part[4*e+1] + part[4*e+2] + part[4*e+3]
                    + router_b[e];
            if (v > bv) { bv = v; best = e; }   // strict > == first-max (jnp.argmax)
        }
        g_idx = best;
    }
}

// Kernel 2: one block per output row, no smem staging.
// Fully unrolled: 4 iterations, all 12 float4 loads batched for max MLP.
__global__ void __launch_bounds__(TPB) gate_mix_kernel(
    const float* __restrict__ x,
    const float* __restrict__ expert_w,
    const float* __restrict__ expert_b,
    const float* __restrict__ gate_w,
    const float* __restrict__ gate_b,
    float* __restrict__ out) {

    const int row = blockIdx.x;
    const int idx = g_idx;

    const float4* x4 = (const float4*)x;
    const float4* e4 = (const float4*)(expert_w + ((size_t)idx * H + row) * H);
    const float4* g4 = (const float4*)(gate_w + (size_t)row * H);

    // Batch all loads up front (independent -> high MLP)
    float4 xa[ITERS], ea[ITERS], ga[ITERS];
    #pragma unroll
    for (int k = 0; k < ITERS; k++) {
        int i = threadIdx.x + k * TPB;
        xa[k] = x4[i];
        ea[k] = e4[i];
        ga[k] = g4[i];
    }

    float se = 0.f, sg = 0.f;
    #pragma unroll
    for (int k = 0; k < ITERS; k++) {
        se += xa[k].x * ea[k].x + xa[k].y * ea[k].y
            + xa[k].z * ea[k].z + xa[k].w * ea[k].w;
        sg += xa[k].x * ga[k].x + xa[k].y * ga[k].y
            + xa[k].z * ga[k].z + xa[k].w * ga[k].w;
    }

    #pragma unroll
    for (int o = 16; o > 0; o >>= 1) {
        se += __shfl_xor_sync(0xFFFFFFFFu, se, o);
        sg += __shfl_xor_sync(0xFFFFFFFFu, sg, o);
    }

    __shared__ float re[TPB / 32], rg[TPB / 32];
    const int wid  = threadIdx.x >> 5;
    const int lane = threadIdx.x & 31;
    if (lane == 0) { re[wid] = se; rg[wid] = sg; }
    __syncthreads();

    if (threadIdx.x == 0) {
        float SE = 0.f, SG = 0.f;
        #pragma unroll
        for (int w = 0; w < TPB / 32; w++) { SE += re[w]; SG += rg[w]; }
        float mix = tanhf(SE + expert_b[(size_t)idx * H + row]);
        float z = SG + gate_b[row];
        float g = 1.f / (1.f + expf(-z));
        float xv = x[row];
        out[row] = g * mix + (1.f - g) * xv;
    }
}

extern "C" void kernel_launch(void* const* d_in, const int* in_sizes, int n_in,
                              void* d_out, int out_size) {
    const float* x        = (const float*)d_in[0];  // [1, H]
    const float* expert_w = (const float*)d_in[1];  // [E, H, H]
    const float* expert_b = (const float*)d_in[2];  // [E, H]
    const float* router_w = (const float*)d_in[3];  // [E, H]
    const float* router_b = (const float*)d_in[4];  // [E]
    const float* gate_w   = (const float*)d_in[5];  // [H, H]
    const float* gate_b   = (const float*)d_in[6];  // [H]
    float* out = (float*)d_out;                     // [1, H]

    router_argmax_kernel<<<1, 1024>>>(x, router_w, router_b);
    gate_mix_kernel<<<H, TPB>>>(x, expert_w, expert_b, gate_w, gate_b, out);
}